// round 8
// baseline (speedup 1.0000x reference)
#include <cuda_runtime.h>
#include <cuda_bf16.h>
#include <cstdint>

#define N_ROIS   32768
#define N_GT     1024
#define N_IMAGES 8
#define NT       512
#define RPB      128                 // ROIs per block
#define NB       (N_ROIS / RPB)      // 256 blocks

// division-free IoU argmax step; ag recomputed from box (saves an LDS)
#define IOU_STEP(J, BI, BU, BJ) {                               \
    float4 g  = sbox[J];                                        \
    float iw  = fminf(rx2p, g.z) - fmaxf(rx1, g.x);             \
    float ih  = fminf(ry2p, g.w) - fmaxf(ry1, g.y);             \
    float inter = fmaxf(iw, 0.0f) * ih;                         \
    float ag  = (g.z - g.x) * (g.w - g.y);                      \
    float uni   = (area_r + ag) - inter;                        \
    bool better = inter * (BU) > (BI) * uni;                    \
    BI = better ? inter : (BI);                                 \
    BU = better ? uni   : (BU);                                 \
    BJ = better ? (J)   : (BJ);                                 \
}

#define MERGE(OBI, OBU, OBJ) {                                  \
    float a = (OBI) * bu, c = bi * (OBU);                       \
    bool take = (a > c) ||                                      \
        (a == c && (unsigned)(OBJ) < (unsigned)bj);             \
    bi = take ? (OBI) : bi;                                     \
    bu = take ? (OBU) : bu;                                     \
    bj = take ? (OBJ) : bj;                                     \
}

__global__ void __launch_bounds__(NT) roitarget_fused(const float* __restrict__ rois,
                                                      const int* __restrict__ rb,
                                                      const float* __restrict__ gt,
                                                      const int* __restrict__ gb,
                                                      float* __restrict__ out) {
    __shared__ float4 sbox[N_GT];          // 16KB compacted x1,y1,x2+1,y2+1
    __shared__ float  slab[N_GT];          // 4KB labels
    __shared__ float4 sroi[RPB];           // 2KB ROI coords by local index
    __shared__ int    sgcnt[32][9];        // per-chunk per-batch GT counts (padded)
    __shared__ int    sexcl[32][9];        // exclusive chunk prefix (padded)
    __shared__ int    stot[N_IMAGES];
    __shared__ int    soff[N_IMAGES + 1];
    __shared__ int    swc[4][8];           // ROI counts per warp/batch
    __shared__ int    wbase[4][8];
    __shared__ int    sprovb[RPB], sprovr[RPB];
    __shared__ int    ssrc[RPB];           // sorted pos -> local ROI index
    __shared__ int    ssb[RPB];            // sorted pos -> batch

    const int tid  = threadIdx.x;
    const int w    = tid >> 5;
    const int lane = tid & 31;
    const unsigned lt = (1u << lane) - 1u;

    // ---- hoisted global loads (latency overlapped with ballot phase) ----
    const int ja = tid, jb = tid + NT;
    const int ba  = gb[ja];
    const int bb2 = gb[jb];
    const float a0 = gt[5*ja+0], a1 = gt[5*ja+1], a2 = gt[5*ja+2], a3 = gt[5*ja+3], a4 = gt[5*ja+4];
    const float c0 = gt[5*jb+0], c1 = gt[5*jb+1], c2 = gt[5*jb+2], c3 = gt[5*jb+3], c4 = gt[5*jb+4];
    int myb = 0;
    if (tid < RPB) {
        const int i = blockIdx.x * RPB + tid;
        myb = rb[i];
        sroi[tid] = make_float4(rois[5*i+0], rois[5*i+1], rois[5*i+2], rois[5*i+3]);
    }

    // ---- ballot counting: GT chunks (all warps) ----
    int ranka = 0, rankb = 0;
#pragma unroll
    for (int b = 0; b < N_IMAGES; b++) {
        unsigned ma = __ballot_sync(0xffffffffu, ba == b);
        if (ba == b) ranka = __popc(ma & lt);
        unsigned mb = __ballot_sync(0xffffffffu, bb2 == b);
        if (bb2 == b) rankb = __popc(mb & lt);
        if (lane == 0) { sgcnt[w][b] = __popc(ma); sgcnt[16 + w][b] = __popc(mb); }
    }
    // ---- ballot counting: ROIs (warps 0-3) ----
    if (tid < RPB) {
        int rank = 0;
#pragma unroll
        for (int b = 0; b < N_IMAGES; b++) {
            unsigned m = __ballot_sync(0xffffffffu, myb == b);
            if (myb == b) rank = __popc(m & lt);
            if (lane == 0) swc[w][b] = __popc(m);
        }
        sprovb[tid] = myb;
        sprovr[tid] = rank;
    }
    __syncthreads();                       // sync 1

    // ---- scans in parallel: warps 0-7 GT chunk-scan, warp 8 ROI bases ----
    if (w < N_IMAGES) {
        int v = sgcnt[lane][w];
        int incl = v;
#pragma unroll
        for (int d = 1; d < 32; d <<= 1) {
            int t = __shfl_up_sync(0xffffffffu, incl, d);
            if (lane >= d) incl += t;
        }
        sexcl[lane][w] = incl - v;
        if (lane == 31) stot[w] = incl;
    } else if (w == 8) {
        int ww = lane >> 3, b2 = lane & 7;
        int o = 0;
        for (int b3 = 0; b3 < b2; b3++)
#pragma unroll
            for (int w2 = 0; w2 < 4; w2++) o += swc[w2][b3];
        for (int w2 = 0; w2 < ww; w2++) o += swc[w2][b2];
        wbase[ww][b2] = o;
    }
    __syncthreads();                       // sync 2

    // ---- soff (1 thread) + ROI scatter (warps 0-3) in same window ----
    if (tid == 0) {
        int o = 0;
        for (int b = 0; b < N_IMAGES; b++) { soff[b] = o; o += stot[b]; }
        soff[N_IMAGES] = o;
    }
    if (tid < RPB) {
        int pb = sprovb[tid];
        int dest = wbase[tid >> 5][pb] + sprovr[tid];
        ssrc[dest] = tid;                  // local index
        ssb[dest]  = pb;
    }
    __syncthreads();                       // sync 3

    // ---- GT scatter (2 per thread, data already in registers) ----
    {
        int da = soff[ba] + sexcl[w][ba] + ranka;
        sbox[da] = make_float4(a0, a1, a2 + 1.0f, a3 + 1.0f);
        slab[da] = a4;
        int db = soff[bb2] + sexcl[16 + w][bb2] + rankb;
        sbox[db] = make_float4(c0, c1, c2 + 1.0f, c3 + 1.0f);
        slab[db] = c4;
    }
    __syncthreads();                       // sync 4

    // ---------------- Phase 3: 4 threads per ROI, interleaved quarters -----
    const int s = tid >> 2;                // ROI slot 0..127
    const int q = tid & 3;                 // quarter
    const int loc = ssrc[s];
    const int b   = ssb[s];
    const int ii  = blockIdx.x * RPB + loc;

    const float4 rr = sroi[loc];
    const float rx1 = rr.x, ry1 = rr.y;
    const float rx2p = rr.z + 1.0f;
    const float ry2p = rr.w + 1.0f;
    const float ew = (rr.z - rx1) + 1.0f;
    const float eh = (rr.w - ry1) + 1.0f;
    const float area_r = ew * eh;

    const int j0 = soff[b];
    const int j1 = soff[b + 1];
    const int len = j1 - j0;
    const int nfull = len >> 4;

    float bi0 = 0.0f, bu0 = 1.0f; int bj0 = -1;
    float bi1 = 0.0f, bu1 = 1.0f; int bj1 = -1;
    float bi2 = 0.0f, bu2 = 1.0f; int bj2 = -1;
    float bi3 = 0.0f, bu3 = 1.0f; int bj3 = -1;

    int base = j0 + q;
    for (int t = 0; t < nfull; t++, base += 16) {
        IOU_STEP(base + 0,  bi0, bu0, bj0);
        IOU_STEP(base + 4,  bi1, bu1, bj1);
        IOU_STEP(base + 8,  bi2, bu2, bj2);
        IOU_STEP(base + 12, bi3, bu3, bj3);
    }
    for (int j = j0 + (nfull << 4) + q; j < j1; j += 4) {
        IOU_STEP(j, bi0, bu0, bj0);
    }

    // in-thread chain merge (ties -> smaller j)
    float bi = bi0, bu = bu0; int bj = bj0;
    MERGE(bi1, bu1, bj1);
    MERGE(bi2, bu2, bj2);
    MERGE(bi3, bu3, bj3);

    // cross-quarter butterfly merge
#pragma unroll
    for (int d = 1; d <= 2; d <<= 1) {
        float obi = __shfl_xor_sync(0xffffffffu, bi, d);
        float obu = __shfl_xor_sync(0xffffffffu, bu, d);
        int   obj = __shfl_xor_sync(0xffffffffu, bj, d);
        MERGE(obi, obu, obj);
    }

    if (q == 0) {
        const float iou = bi / bu;
        const bool  fg  = (bj >= 0) && (iou >= 0.5f);

        float lbl = 0.0f, dx = 0.0f, dy = 0.0f, dw = 0.0f, dh = 0.0f, wgt = 0.0f;
        if (fg) {
            float4 g = sbox[bj];
            float gw  = g.z - g.x;             // (x2+1) - x1
            float gh  = g.w - g.y;
            float gcx = g.x + 0.5f * gw;
            float gcy = g.y + 0.5f * gh;
            float ecx = rx1 + 0.5f * ew;
            float ecy = ry1 + 0.5f * eh;
            dx = (gcx - ecx) / ew;
            dy = (gcy - ecy) / eh;
            dw = logf(gw / ew);
            dh = logf(gh / eh);
            lbl = slab[bj];
            wgt = 1.0f;
        }

        // Layout: labels[N] | deltas[N][4] | bbwgts[N][1]
        out[ii] = lbl;
        reinterpret_cast<float4*>(out + N_ROIS)[ii] = make_float4(dx, dy, dw, dh);
        out[N_ROIS * 5 + ii] = wgt;
    }
}

extern "C" void kernel_launch(void* const* d_in, const int* in_sizes, int n_in,
                              void* d_out, int out_size) {
    const float* rois = (const float*)d_in[0];
    const int*   rb   = (const int*)d_in[1];
    const float* gt   = (const float*)d_in[2];
    const int*   gb   = (const int*)d_in[3];
    float* out = (float*)d_out;

    roitarget_fused<<<NB, NT>>>(rois, rb, gt, gb, out);
}

// round 9
// speedup vs baseline: 1.0200x; 1.0200x over previous
#include <cuda_runtime.h>
#include <cuda_bf16.h>
#include <cstdint>

#define N_ROIS   32768
#define N_GT     1024
#define N_IMAGES 8
#define NT       512
#define RPB      128                 // ROIs per block
#define NB       (N_ROIS / RPB)      // 256 blocks

// approx-rcp IoU argmax step (MUFU.RCP + FMUL; feeds comparisons only)
#define IOU_STEP(J, BB, BJ) {                                   \
    float4 g  = sbox[J];                                        \
    float iw  = fminf(rx2p, g.z) - fmaxf(rx1, g.x);             \
    float ih  = fminf(ry2p, g.w) - fmaxf(ry1, g.y);             \
    float inter = fmaxf(iw, 0.0f) * ih;                         \
    float uni = (g.z - g.x) * (g.w - g.y) + (area_r - inter);   \
    float iouv = __fdividef(inter, uni);                        \
    bool better = iouv > (BB);                                  \
    BB = better ? iouv : (BB);                                  \
    BJ = better ? (J)  : (BJ);                                  \
}

// merge: greater iou wins; exact tie -> smaller j (sentinel -1 never wins ties)
#define MERGE(OB, OJ) {                                         \
    bool take = ((OB) > best) ||                                \
        ((OB) == best && (unsigned)(OJ) < (unsigned)bj);        \
    best = take ? (OB) : best;                                  \
    bj   = take ? (OJ) : bj;                                    \
}

__global__ void __launch_bounds__(NT) roitarget_fused(const float* __restrict__ rois,
                                                      const int* __restrict__ rb,
                                                      const float* __restrict__ gt,
                                                      const int* __restrict__ gb,
                                                      float* __restrict__ out) {
    __shared__ float4 sbox[N_GT];          // 16KB compacted x1,y1,x2+1,y2+1
    __shared__ float  slab[N_GT];          // 4KB labels
    __shared__ float4 sroi[RPB];           // 2KB ROI coords by local index
    __shared__ int    sgcnt[32][9];        // per-chunk per-batch GT counts (padded)
    __shared__ int    sexcl[32][9];        // exclusive chunk prefix (padded)
    __shared__ int    stot[N_IMAGES];
    __shared__ int    soff[N_IMAGES + 1];
    __shared__ int    swc[4][8];           // ROI counts per warp/batch
    __shared__ int    wbase[4][8];
    __shared__ int    sprovb[RPB], sprovr[RPB];
    __shared__ int    ssrc[RPB];           // sorted pos -> local ROI index
    __shared__ int    ssb[RPB];            // sorted pos -> batch

    const int tid  = threadIdx.x;
    const int w    = tid >> 5;
    const int lane = tid & 31;
    const unsigned lt = (1u << lane) - 1u;

    // ---- hoisted global loads (latency overlapped with ballot phase) ----
    const int ja = tid, jb = tid + NT;
    const int ba  = gb[ja];
    const int bb2 = gb[jb];
    const float a0 = gt[5*ja+0], a1 = gt[5*ja+1], a2 = gt[5*ja+2], a3 = gt[5*ja+3], a4 = gt[5*ja+4];
    const float c0 = gt[5*jb+0], c1 = gt[5*jb+1], c2 = gt[5*jb+2], c3 = gt[5*jb+3], c4 = gt[5*jb+4];
    int myb = 0;
    if (tid < RPB) {
        const int i = blockIdx.x * RPB + tid;
        myb = rb[i];
        sroi[tid] = make_float4(rois[5*i+0], rois[5*i+1], rois[5*i+2], rois[5*i+3]);
    }

    // ---- ballot counting: GT chunks (all warps) ----
    int ranka = 0, rankb = 0;
#pragma unroll
    for (int b = 0; b < N_IMAGES; b++) {
        unsigned ma = __ballot_sync(0xffffffffu, ba == b);
        if (ba == b) ranka = __popc(ma & lt);
        unsigned mb = __ballot_sync(0xffffffffu, bb2 == b);
        if (bb2 == b) rankb = __popc(mb & lt);
        if (lane == 0) { sgcnt[w][b] = __popc(ma); sgcnt[16 + w][b] = __popc(mb); }
    }
    // ---- ballot counting: ROIs (warps 0-3) ----
    if (tid < RPB) {
        int rank = 0;
#pragma unroll
        for (int b = 0; b < N_IMAGES; b++) {
            unsigned m = __ballot_sync(0xffffffffu, myb == b);
            if (myb == b) rank = __popc(m & lt);
            if (lane == 0) swc[w][b] = __popc(m);
        }
        sprovb[tid] = myb;
        sprovr[tid] = rank;
    }
    __syncthreads();                       // sync 1

    // ---- scans in parallel: warps 0-7 GT chunk-scan, warp 8 ROI bases ----
    if (w < N_IMAGES) {
        int v = sgcnt[lane][w];
        int incl = v;
#pragma unroll
        for (int d = 1; d < 32; d <<= 1) {
            int t = __shfl_up_sync(0xffffffffu, incl, d);
            if (lane >= d) incl += t;
        }
        sexcl[lane][w] = incl - v;
        if (lane == 31) stot[w] = incl;
    } else if (w == 8) {
        int ww = lane >> 3, b2 = lane & 7;
        int o = 0;
        for (int b3 = 0; b3 < b2; b3++)
#pragma unroll
            for (int w2 = 0; w2 < 4; w2++) o += swc[w2][b3];
        for (int w2 = 0; w2 < ww; w2++) o += swc[w2][b2];
        wbase[ww][b2] = o;
    }
    __syncthreads();                       // sync 2

    // ---- per-warp redundant soff compute (identical values; no extra barrier)
    if (lane == 0) {
        int o = 0;
#pragma unroll
        for (int b = 0; b < N_IMAGES; b++) { soff[b] = o; o += stot[b]; }
        soff[N_IMAGES] = o;
    }
    __syncwarp();

    // ---- GT scatter (2 per thread, data already in registers) ----
    {
        int da = soff[ba] + sexcl[w][ba] + ranka;
        sbox[da] = make_float4(a0, a1, a2 + 1.0f, a3 + 1.0f);
        slab[da] = a4;
        int db = soff[bb2] + sexcl[16 + w][bb2] + rankb;
        sbox[db] = make_float4(c0, c1, c2 + 1.0f, c3 + 1.0f);
        slab[db] = c4;
    }
    // ---- ROI scatter (warps 0-3) in same window ----
    if (tid < RPB) {
        int pb = sprovb[tid];
        int dest = wbase[tid >> 5][pb] + sprovr[tid];
        ssrc[dest] = tid;                  // local index
        ssb[dest]  = pb;
    }
    __syncthreads();                       // sync 3

    // ---------------- Phase 3: 4 threads per ROI, interleaved quarters -----
    const int s = tid >> 2;                // ROI slot 0..127
    const int q = tid & 3;                 // quarter
    const int loc = ssrc[s];
    const int b   = ssb[s];
    const int ii  = blockIdx.x * RPB + loc;

    const float4 rr = sroi[loc];
    const float rx1 = rr.x, ry1 = rr.y;
    const float rx2p = rr.z + 1.0f;
    const float ry2p = rr.w + 1.0f;
    const float ew = (rr.z - rx1) + 1.0f;
    const float eh = (rr.w - ry1) + 1.0f;
    const float area_r = ew * eh;

    const int j0 = soff[b];
    const int j1 = soff[b + 1];
    const int len = j1 - j0;
    const int nfull = len >> 4;

    float bb0 = 0.0f; int bj0 = -1;
    float bb1 = 0.0f; int bj1 = -1;
    float bb3 = 0.0f; int bj3 = -1;
    float bb4 = 0.0f; int bj4 = -1;

    int base = j0 + q;
    for (int t = 0; t < nfull; t++, base += 16) {
        IOU_STEP(base + 0,  bb0, bj0);
        IOU_STEP(base + 4,  bb1, bj1);
        IOU_STEP(base + 8,  bb3, bj3);
        IOU_STEP(base + 12, bb4, bj4);
    }
    for (int j = j0 + (nfull << 4) + q; j < j1; j += 4) {
        IOU_STEP(j, bb0, bj0);
    }

    // in-thread chain merge (ties -> smaller j)
    float best = bb0; int bj = bj0;
    MERGE(bb1, bj1);
    MERGE(bb3, bj3);
    MERGE(bb4, bj4);

    // cross-quarter butterfly merge
#pragma unroll
    for (int d = 1; d <= 2; d <<= 1) {
        float ob = __shfl_xor_sync(0xffffffffu, best, d);
        int   oj = __shfl_xor_sync(0xffffffffu, bj, d);
        MERGE(ob, oj);
    }

    if (q == 0) {
        const bool fg = (bj >= 0) && (best >= 0.5f);

        float lbl = 0.0f, dx = 0.0f, dy = 0.0f, dw = 0.0f, dh = 0.0f, wgt = 0.0f;
        if (fg) {
            float4 g = sbox[bj];
            float gw  = g.z - g.x;             // (x2+1) - x1
            float gh  = g.w - g.y;
            float gcx = g.x + 0.5f * gw;
            float gcy = g.y + 0.5f * gh;
            float ecx = rx1 + 0.5f * ew;
            float ecy = ry1 + 0.5f * eh;
            dx = (gcx - ecx) / ew;             // precise: feeds output
            dy = (gcy - ecy) / eh;
            dw = logf(gw / ew);
            dh = logf(gh / eh);
            lbl = slab[bj];
            wgt = 1.0f;
        }

        // Layout: labels[N] | deltas[N][4] | bbwgts[N][1]
        out[ii] = lbl;
        reinterpret_cast<float4*>(out + N_ROIS)[ii] = make_float4(dx, dy, dw, dh);
        out[N_ROIS * 5 + ii] = wgt;
    }
}

extern "C" void kernel_launch(void* const* d_in, const int* in_sizes, int n_in,
                              void* d_out, int out_size) {
    const float* rois = (const float*)d_in[0];
    const int*   rb   = (const int*)d_in[1];
    const float* gt   = (const float*)d_in[2];
    const int*   gb   = (const int*)d_in[3];
    float* out = (float*)d_out;

    roitarget_fused<<<NB, NT>>>(rois, rb, gt, gb, out);
}